// round 8
// baseline (speedup 1.0000x reference)
#include <cuda_runtime.h>
#include <cuda_bf16.h>

// NCEAverage: B=256, D=128, N=1e6, K1=2048, T=0.07, MOMENTUM=0.5
// Output: [ out_l(B*K1) | out_ab(B*K1) | new_memory_l(N*D) | new_memory_ab(N*D) ]
//
// Structure (R8):
//   - bucket build: memset counts + 1 scatter kernel + tiny mark kernel
//   - pass 1: stream bank_l  -> out_ml, scoring dot(mem_l[r], ab[b]) -> out_ab,
//             rows in y-set get EMA+normalized value written instead of copy
//   - pass 2: same for bank_ab / l / out_l
//   - overflow fixup kernel (expected empty)

#define DIM      128
#define T_INV    (1.0f / 0.07f)
#define N_MAX    1048576
#define CAP      12

__device__ int g_count[N_MAX];
__device__ int g_upd  [N_MAX];          // b+1 of LAST occurrence in y, else 0
__device__ int g_tasks[N_MAX * CAP];
__device__ int g_ovf  [4096];
__device__ int g_novf;

// ---------------- build ----------------
__global__ void k_scatter(const int* __restrict__ idx, int bk) {
    for (int t = blockIdx.x * blockDim.x + threadIdx.x; t < bk;
         t += gridDim.x * blockDim.x) {
        const int row  = idx[t];
        const int slot = atomicAdd(&g_count[row], 1);
        if (slot < CAP) g_tasks[row * CAP + slot] = t;
        else            g_ovf[atomicAdd(&g_novf, 1)] = t;
    }
}

__global__ void k_mark(const int* __restrict__ y, int B) {
    const int b = threadIdx.x;
    if (b < B) atomicMax(&g_upd[y[b]], b + 1);
}

// ---------------- streaming pass: copy + score + folded update --------------
// One warp per row. v = old row (used for scoring). If row is in the y-set,
// the written value is the EMA+normalized update instead of the copy.
__global__ void __launch_bounds__(256) stream_score(
    const float4* __restrict__ bank, float4* __restrict__ outb,
    const float4* __restrict__ query,   // q[b] dotted against this bank
    const float4* __restrict__ upd_vec, // vector EMA'd into this bank
    float* __restrict__ out_score,
    int Nrows, int K1)
{
    const int lane = threadIdx.x & 31;
    const int nw   = gridDim.x * (blockDim.x >> 5);
    int r          = blockIdx.x * (blockDim.x >> 5) + (threadIdx.x >> 5);

    if (r >= Nrows) return;
    float4 v = __ldcs(&bank[(long long)r * 32 + lane]);

    while (true) {
        const int rn = r + nw;
        float4 vn;
        if (rn < Nrows) vn = __ldcs(&bank[(long long)rn * 32 + lane]);  // prefetch

        // ---- write: copy, or EMA+normalize for updated rows ----
        const int ub = g_upd[r];
        if (ub == 0) {
            __stcs(&outb[(long long)r * 32 + lane], v);
        } else {
            const float4 u = upd_vec[(ub - 1) * 32 + lane];
            float4 w;
            w.x = 0.5f * v.x + 0.5f * u.x;
            w.y = 0.5f * v.y + 0.5f * u.y;
            w.z = 0.5f * v.z + 0.5f * u.z;
            w.w = 0.5f * v.w + 0.5f * u.w;
            float ss = w.x * w.x + w.y * w.y + w.z * w.z + w.w * w.w;
            #pragma unroll
            for (int o = 16; o; o >>= 1) ss += __shfl_xor_sync(0xffffffffu, ss, o);
            const float inv = rsqrtf(ss);
            w.x *= inv; w.y *= inv; w.z *= inv; w.w *= inv;
            __stcs(&outb[(long long)r * 32 + lane], w);
        }

        // ---- score tasks on this row (against OLD value v) ----
        int cnt = g_count[r];
        if (cnt) {
            if (cnt > CAP) cnt = CAP;
            const int base = r * CAP;
            for (int j = 0; j < cnt; ++j) {
                const int task = g_tasks[base + j];
                const int b    = task / K1;
                const float4 q = query[b * 32 + lane];
                float s = v.x * q.x + v.y * q.y + v.z * q.z + v.w * q.w;
                #pragma unroll
                for (int o = 16; o; o >>= 1) s += __shfl_xor_sync(0xffffffffu, s, o);
                if (lane == 0) out_score[task] = s * T_INV;
            }
        }
        if (rn >= Nrows) break;
        r = rn;
        v = vn;
    }
}

// ---------------- overflow fixup (expected: zero tasks) ----------------
__global__ void __launch_bounds__(256) k_overflow(
    const float* __restrict__ mem_l, const float* __restrict__ mem_ab,
    const float4* __restrict__ ql, const float4* __restrict__ qab,
    const int* __restrict__ idx,
    float* __restrict__ out_l, float* __restrict__ out_ab, int K1)
{
    const int n = g_novf;
    const int lane = threadIdx.x & 31;
    for (int i = threadIdx.x >> 5; i < n; i += 8) {
        const int task = g_ovf[i];
        const int b    = task / K1;
        const long long row = idx[task];
        const float4 wl  = ((const float4*)(mem_l  + row * DIM))[lane];
        const float4 wab = ((const float4*)(mem_ab + row * DIM))[lane];
        const float4 q1  = qab[b * 32 + lane];
        const float4 q2  = ql [b * 32 + lane];
        float s1 = wl.x * q1.x + wl.y * q1.y + wl.z * q1.z + wl.w * q1.w;
        float s2 = wab.x * q2.x + wab.y * q2.y + wab.z * q2.z + wab.w * q2.w;
        #pragma unroll
        for (int o = 16; o; o >>= 1) {
            s1 += __shfl_xor_sync(0xffffffffu, s1, o);
            s2 += __shfl_xor_sync(0xffffffffu, s2, o);
        }
        if (lane == 0) {
            out_ab[task] = s1 * T_INV;
            out_l [task] = s2 * T_INV;
        }
    }
}

extern "C" void kernel_launch(void* const* d_in, const int* in_sizes, int n_in,
                              void* d_out, int out_size)
{
    const float* l      = (const float*)d_in[0];
    const float* ab     = (const float*)d_in[1];
    const int*   y      = (const int*)  d_in[2];
    const int*   idx    = (const int*)  d_in[3];
    const float* mem_l  = (const float*)d_in[4];
    const float* mem_ab = (const float*)d_in[5];

    const int       B     = in_sizes[2];
    const int       BK    = in_sizes[3];
    const int       K1    = BK / B;
    const long long ND    = (long long)in_sizes[4];
    const int       Nrows = (int)(ND / DIM);

    float* out = (float*)d_out;
    float* out_l   = out;
    float* out_ab  = out + BK;
    float* out_ml  = out + 2LL * BK;
    float* out_mab = out + 2LL * BK + ND;

    // ---- reset metadata (no allocation; graph-capturable) ----
    void* p_count; cudaGetSymbolAddress(&p_count, g_count);
    void* p_upd;   cudaGetSymbolAddress(&p_upd,   g_upd);
    void* p_novf;  cudaGetSymbolAddress(&p_novf,  g_novf);
    cudaMemsetAsync(p_count, 0, (size_t)Nrows * sizeof(int));
    cudaMemsetAsync(p_upd,   0, (size_t)Nrows * sizeof(int));
    cudaMemsetAsync(p_novf,  0, sizeof(int));

    // ---- build: row->task buckets + update markers ----
    k_scatter<<<512, 1024>>>(idx, BK);
    k_mark<<<1, 256>>>(y, B);

    // ---- pass 1: bank_l -> out_ml, score vs ab -> out_ab, update with l ----
    stream_score<<<148 * 8, 256>>>((const float4*)mem_l, (float4*)out_ml,
                                   (const float4*)ab, (const float4*)l,
                                   out_ab, Nrows, K1);

    // ---- pass 2: bank_ab -> out_mab, score vs l -> out_l, update with ab ----
    stream_score<<<148 * 8, 256>>>((const float4*)mem_ab, (float4*)out_mab,
                                   (const float4*)l, (const float4*)ab,
                                   out_l, Nrows, K1);

    // ---- overflow tasks (expected none) ----
    k_overflow<<<1, 256>>>(mem_l, mem_ab, (const float4*)l, (const float4*)ab,
                           idx, out_l, out_ab, K1);
}

// round 9
// speedup vs baseline: 1.1612x; 1.1612x over previous
#include <cuda_runtime.h>
#include <cuda_bf16.h>

// NCEAverage: B=256, D=128, N=1e6, K1=2048, T=0.07, MOMENTUM=0.5
// Output: [ out_l(B*K1) | out_ab(B*K1) | new_memory_l(N*D) | new_memory_ab(N*D) ]
//
// R9 = R4 pass structure (unconditional store; metadata never gates the copy
// stream) + cheap bucket build + count prefetch. Separate row-update kernel.

#define DIM      128
#define T_INV    (1.0f / 0.07f)
#define N_MAX    1048576
#define CAP      12

__device__ int g_count[N_MAX];
__device__ int g_tasks[N_MAX * CAP];
__device__ int g_ovf  [4096];
__device__ int g_novf;

// ---------------- build: bucket scatter ----------------
__global__ void k_scatter(const int* __restrict__ idx, int bk) {
    for (int t = blockIdx.x * blockDim.x + threadIdx.x; t < bk;
         t += gridDim.x * blockDim.x) {
        const int row  = idx[t];
        const int slot = atomicAdd(&g_count[row], 1);
        if (slot < CAP) g_tasks[row * CAP + slot] = t;
        else            g_ovf[atomicAdd(&g_novf, 1)] = t;
    }
}

// ---------------- streaming pass: copy + score ----------------
// One warp per row. Store depends ONLY on the streamed value v; the task
// count for the NEXT row is prefetched with the next row's data.
__global__ void __launch_bounds__(256) stream_score(
    const float4* __restrict__ bank, float4* __restrict__ outb,
    const float4* __restrict__ query, float* __restrict__ out_score,
    int Nrows, int K1)
{
    const int lane = threadIdx.x & 31;
    const int nw   = gridDim.x * (blockDim.x >> 5);
    int r          = blockIdx.x * (blockDim.x >> 5) + (threadIdx.x >> 5);

    if (r >= Nrows) return;
    float4 v   = __ldcs(&bank[(long long)r * 32 + lane]);
    int    cnt = g_count[r];

    while (true) {
        const int rn = r + nw;
        float4 vn;
        int    cn = 0;
        if (rn < Nrows) {                      // prefetch next row + its count
            vn = __ldcs(&bank[(long long)rn * 32 + lane]);
            cn = g_count[rn];
        }

        __stcs(&outb[(long long)r * 32 + lane], v);   // unconditional copy

        if (cnt) {
            if (cnt > CAP) cnt = CAP;
            const int base = r * CAP;
            for (int j = 0; j < cnt; ++j) {
                const int task = g_tasks[base + j];
                const int b    = task / K1;
                const float4 q = query[b * 32 + lane];
                float s = v.x * q.x + v.y * q.y + v.z * q.z + v.w * q.w;
                #pragma unroll
                for (int o = 16; o; o >>= 1) s += __shfl_xor_sync(0xffffffffu, s, o);
                if (lane == 0) out_score[task] = s * T_INV;
            }
        }
        if (rn >= Nrows) break;
        r   = rn;
        v   = vn;
        cnt = cn;
    }
}

// ---------------- overflow fixup (expected: zero tasks) ----------------
__global__ void __launch_bounds__(256) k_overflow(
    const float* __restrict__ mem_l, const float* __restrict__ mem_ab,
    const float4* __restrict__ ql, const float4* __restrict__ qab,
    const int* __restrict__ idx,
    float* __restrict__ out_l, float* __restrict__ out_ab, int K1)
{
    const int n = g_novf;
    const int lane = threadIdx.x & 31;
    for (int i = threadIdx.x >> 5; i < n; i += 8) {
        const int task = g_ovf[i];
        const int b    = task / K1;
        const long long row = idx[task];
        const float4 wl  = ((const float4*)(mem_l  + row * DIM))[lane];
        const float4 wab = ((const float4*)(mem_ab + row * DIM))[lane];
        const float4 q1  = qab[b * 32 + lane];
        const float4 q2  = ql [b * 32 + lane];
        float s1 = wl.x * q1.x + wl.y * q1.y + wl.z * q1.z + wl.w * q1.w;
        float s2 = wab.x * q2.x + wab.y * q2.y + wab.z * q2.z + wab.w * q2.w;
        #pragma unroll
        for (int o = 16; o; o >>= 1) {
            s1 += __shfl_xor_sync(0xffffffffu, s1, o);
            s2 += __shfl_xor_sync(0xffffffffu, s2, o);
        }
        if (lane == 0) {
            out_ab[task] = s1 * T_INV;
            out_l [task] = s2 * T_INV;
        }
    }
}

// ---------------- EMA + normalize + scatter (last-occurrence wins) ----------
__global__ void __launch_bounds__(DIM) update_kernel(
    const float* __restrict__ l, const float* __restrict__ ab,
    const int* __restrict__ y,
    const float* __restrict__ mem_l, const float* __restrict__ mem_ab,
    float* __restrict__ out_ml, float* __restrict__ out_mab, int B)
{
    const int b   = blockIdx.x;
    const int tid = threadIdx.x;

    __shared__ int skip;
    __shared__ int yy_s;
    if (tid == 0) { skip = 0; yy_s = y[b]; }
    __syncthreads();
    const int yy = yy_s;
    for (int j = b + 1 + tid; j < B; j += DIM)
        if (y[j] == yy) skip = 1;     // benign race
    __syncthreads();
    if (skip) return;

    const long long r = yy;
    const float vl  = 0.5f * mem_l [r * DIM + tid] + 0.5f * l [b * DIM + tid];
    const float vab = 0.5f * mem_ab[r * DIM + tid] + 0.5f * ab[b * DIM + tid];

    float sl = vl * vl, sab = vab * vab;
    #pragma unroll
    for (int off = 16; off; off >>= 1) {
        sl  += __shfl_xor_sync(0xffffffffu, sl,  off);
        sab += __shfl_xor_sync(0xffffffffu, sab, off);
    }
    __shared__ float wsl[4], wsab[4];
    const int w = tid >> 5, lane = tid & 31;
    if (lane == 0) { wsl[w] = sl; wsab[w] = sab; }
    __syncthreads();
    const float tsl  = wsl[0]  + wsl[1]  + wsl[2]  + wsl[3];
    const float tsab = wsab[0] + wsab[1] + wsab[2] + wsab[3];

    out_ml [r * DIM + tid] = vl  * rsqrtf(tsl);
    out_mab[r * DIM + tid] = vab * rsqrtf(tsab);
}

extern "C" void kernel_launch(void* const* d_in, const int* in_sizes, int n_in,
                              void* d_out, int out_size)
{
    const float* l      = (const float*)d_in[0];
    const float* ab     = (const float*)d_in[1];
    const int*   y      = (const int*)  d_in[2];
    const int*   idx    = (const int*)  d_in[3];
    const float* mem_l  = (const float*)d_in[4];
    const float* mem_ab = (const float*)d_in[5];

    const int       B     = in_sizes[2];
    const int       BK    = in_sizes[3];
    const int       K1    = BK / B;
    const long long ND    = (long long)in_sizes[4];
    const int       Nrows = (int)(ND / DIM);

    float* out = (float*)d_out;
    float* out_l   = out;
    float* out_ab  = out + BK;
    float* out_ml  = out + 2LL * BK;
    float* out_mab = out + 2LL * BK + ND;

    // ---- reset metadata (no allocation; graph-capturable) ----
    void* p_count; cudaGetSymbolAddress(&p_count, g_count);
    void* p_novf;  cudaGetSymbolAddress(&p_novf,  g_novf);
    cudaMemsetAsync(p_count, 0, (size_t)Nrows * sizeof(int));
    cudaMemsetAsync(p_novf,  0, sizeof(int));

    // ---- build: row->task buckets ----
    k_scatter<<<512, 1024>>>(idx, BK);

    // ---- pass 1: bank_l -> out_ml, score vs ab -> out_ab ----
    stream_score<<<148 * 8, 256>>>((const float4*)mem_l, (float4*)out_ml,
                                   (const float4*)ab, out_ab, Nrows, K1);

    // ---- pass 2: bank_ab -> out_mab, score vs l -> out_l ----
    stream_score<<<148 * 8, 256>>>((const float4*)mem_ab, (float4*)out_mab,
                                   (const float4*)l, out_l, Nrows, K1);

    // ---- overflow tasks (expected none) ----
    k_overflow<<<1, 256>>>(mem_l, mem_ab, (const float4*)l, (const float4*)ab,
                           idx, out_l, out_ab, K1);

    // ---- row updates (after the copies; reads OLD memory from inputs) ----
    update_kernel<<<B, DIM>>>(l, ab, y, mem_l, mem_ab, out_ml, out_mab, B);
}